// round 1
// baseline (speedup 1.0000x reference)
#include <cuda_runtime.h>

#define DH 64
#define MAX_BH 256

// Scratch: per-(b,h) 64x64 context matrix + 64-entry v2 column sum.
__device__ float g_ctx[MAX_BH * DH * DH];
__device__ float g_vsum[MAX_BH * DH];

typedef unsigned long long u64t;

__device__ __forceinline__ u64t pk2(float lo, float hi) {
    u64t r; asm("mov.b64 %0, {%1, %2};" : "=l"(r) : "f"(lo), "f"(hi)); return r;
}
__device__ __forceinline__ void upk2(u64t v, float& lo, float& hi) {
    asm("mov.b64 {%0, %1}, %2;" : "=f"(lo), "=f"(hi) : "l"(v));
}
// Packed dual-FMA (Blackwell f32x2 pipe): acc.lo += a.lo*b.lo ; acc.hi += a.hi*b.hi
__device__ __forceinline__ void fma2(u64t& acc, u64t a, u64t b) {
    asm("fma.rn.f32x2 %0, %1, %2, %0;" : "+l"(acc) : "l"(a), "l"(b));
}
// elu(v) + 1
__device__ __forceinline__ float elu1(float v) { return v > 0.f ? v + 1.f : __expf(v); }

__global__ void zero_kernel(int nctx, int nvs)
{
    int i = blockIdx.x * blockDim.x + threadIdx.x;
    if (i < nctx) g_ctx[i] = 0.f;
    if (i < nvs)  g_vsum[i] = 0.f;
}

// ---------------------------------------------------------------------------
// Kernel A: accumulate ctx[d][e] = sum_n v2[n,d] * x[n,e]  and  vsum[d] = sum_n v2[n,d]
// Grid: (splits, BH). Block: 256 threads. Tiles of 32 rows.
// ---------------------------------------------------------------------------
__global__ void __launch_bounds__(256)
ctx_kernel(const float* __restrict__ Kg, const float* __restrict__ Vg,
           const float* __restrict__ mask, const float* __restrict__ c,
           int csize, int N)
{
    const int bh   = blockIdx.y;
    const int rows = N / gridDim.x;
    const int n0   = blockIdx.x * rows;
    const float k  = (csize > 1) ? c[bh % csize] : c[0];

    const float* Kp = Kg + (size_t)bh * N * DH;
    const float* Vp = Vg + (size_t)bh * N * DH;

    __shared__ float v2_s[32][DH];
    __shared__ float x_s[32][DH];

    const int tid  = threadIdx.x;
    const int lrow = tid >> 3;          // 0..31  (row within tile)
    const int lcol = (tid & 7) << 3;    // 0,8,..,56 (8 cols per thread)
    const int ty   = tid >> 4;          // 0..15  (compute mapping: 4 d-rows)
    const int tx   = tid & 15;          // 0..15  (compute mapping: 4 e-cols)

    u64t acc[4][2];
    #pragma unroll
    for (int i = 0; i < 4; i++) { acc[i][0] = pk2(0.f, 0.f); acc[i][1] = pk2(0.f, 0.f); }
    float vsum[8] = {0.f,0.f,0.f,0.f,0.f,0.f,0.f,0.f};

    for (int t0 = 0; t0 < rows; t0 += 32) {
        const int n = n0 + t0 + lrow;
        const size_t nb = (size_t)n * DH;

        // --- elementwise phase: 8 lanes per row ---
        const float4 va = *(const float4*)(Vp + nb + lcol);
        const float4 vb = *(const float4*)(Vp + nb + lcol + 4);
        float ss = va.x*va.x + va.y*va.y + va.z*va.z + va.w*va.w
                 + vb.x*vb.x + vb.y*vb.y + vb.z*vb.z + vb.w*vb.w;
        ss += __shfl_xor_sync(0xffffffffu, ss, 1);
        ss += __shfl_xor_sync(0xffffffffu, ss, 2);
        ss += __shfl_xor_sync(0xffffffffu, ss, 4);
        const float denom = fmaxf(fmaf(k, ss, 1.f), 1e-15f);
        const float rinv  = 1.f / denom;
        const float g     = 2.f * rinv;
        const float gm1   = g - 1.f;
        const float sgn   = (gm1 >= 0.f) ? 1.f : -1.f;
        const float d2    = sgn * fmaxf(fabsf(gm1), 1e-10f);
        const float m     = mask[n];
        const float xs    = g / d2 * m;
        const float d2m   = d2 * m;

        float* xr = &x_s[lrow][lcol];
        xr[0] = va.x*xs; xr[1] = va.y*xs; xr[2] = va.z*xs; xr[3] = va.w*xs;
        xr[4] = vb.x*xs; xr[5] = vb.y*xs; xr[6] = vb.z*xs; xr[7] = vb.w*xs;

        const float4 ka = *(const float4*)(Kp + nb + lcol);
        const float4 kb = *(const float4*)(Kp + nb + lcol + 4);
        float w[8];
        w[0] = d2m*elu1(ka.x*rinv); w[1] = d2m*elu1(ka.y*rinv);
        w[2] = d2m*elu1(ka.z*rinv); w[3] = d2m*elu1(ka.w*rinv);
        w[4] = d2m*elu1(kb.x*rinv); w[5] = d2m*elu1(kb.y*rinv);
        w[6] = d2m*elu1(kb.z*rinv); w[7] = d2m*elu1(kb.w*rinv);
        float* wr = &v2_s[lrow][lcol];
        #pragma unroll
        for (int j = 0; j < 8; j++) { wr[j] = w[j]; vsum[j] += w[j]; }
        __syncthreads();

        // --- rank-32 update of the 64x64 context: thread owns 4x4 tile ---
        #pragma unroll
        for (int t = 0; t < 32; t++) {
            const float4 a = *(const float4*)&v2_s[t][ty * 4];
            const float4 b = *(const float4*)&x_s[t][tx * 4];
            const u64t b01 = pk2(b.x, b.y), b23 = pk2(b.z, b.w);
            u64t ax;
            ax = pk2(a.x, a.x); fma2(acc[0][0], ax, b01); fma2(acc[0][1], ax, b23);
            ax = pk2(a.y, a.y); fma2(acc[1][0], ax, b01); fma2(acc[1][1], ax, b23);
            ax = pk2(a.z, a.z); fma2(acc[2][0], ax, b01); fma2(acc[2][1], ax, b23);
            ax = pk2(a.w, a.w); fma2(acc[3][0], ax, b01); fma2(acc[3][1], ax, b23);
        }
        __syncthreads();
    }

    // --- commit ctx partials ---
    float* ctx = g_ctx + (size_t)bh * DH * DH;
    #pragma unroll
    for (int i = 0; i < 4; i++) {
        float e0, e1, e2, e3;
        upk2(acc[i][0], e0, e1);
        upk2(acc[i][1], e2, e3);
        float* row = ctx + (ty * 4 + i) * DH + tx * 4;
        atomicAdd(row + 0, e0); atomicAdd(row + 1, e1);
        atomicAdd(row + 2, e2); atomicAdd(row + 3, e3);
    }

    // --- commit vsum partials (reduce 32 per-thread partials per column) ---
    #pragma unroll
    for (int j = 0; j < 8; j++) v2_s[lrow][lcol + j] = vsum[j];
    __syncthreads();
    if (tid < DH) {
        float s = 0.f;
        #pragma unroll
        for (int r = 0; r < 32; r++) s += v2_s[r][tid];
        atomicAdd(&g_vsum[bh * DH + tid], s);
    }
}

// ---------------------------------------------------------------------------
// Kernel B: per row  X = (v1 @ ctx) / (v1 . vsum), then project -> mobius(0.5) -> project
// Grid: (splits, BH). Block: 256 threads; 8 lanes per row.
// ---------------------------------------------------------------------------
__global__ void __launch_bounds__(256)
out_kernel(const float* __restrict__ Qg, const float* __restrict__ Vg,
           const float* __restrict__ c, int csize, int N, float* __restrict__ out)
{
    const int bh   = blockIdx.y;
    const int rows = N / gridDim.x;
    const int n0   = blockIdx.x * rows;
    const float k  = (csize > 1) ? c[bh % csize] : c[0];
    const float sk = sqrtf(fabsf(k) + 1e-15f);
    const float maxnorm = (k < 0.f) ? (1.f - 0.004f) / sk : 1e15f;
    const bool  hyp = (k < 0.f);

    __shared__ float ctx_s[DH][DH];
    __shared__ float vs_s[DH];
    __shared__ float v1_s[32][DH];

    const int tid = threadIdx.x;
    const float* ctxg = g_ctx + (size_t)bh * DH * DH;
    for (int i = tid; i < DH * DH; i += 256) ctx_s[i >> 6][i & 63] = ctxg[i];
    if (tid < DH) vs_s[tid] = g_vsum[bh * DH + tid];
    __syncthreads();

    const int lrow = tid >> 3;
    const int lcol = (tid & 7) << 3;
    const float* Qp = Qg + (size_t)bh * N * DH;
    const float* Vp = Vg + (size_t)bh * N * DH;
    float*       Op = out + (size_t)bh * N * DH;

    for (int t0 = 0; t0 < rows; t0 += 32) {
        const size_t nb = (size_t)(n0 + t0 + lrow) * DH;

        // --- elementwise: denom from V, v1 from Q, Dn = v1 . vsum ---
        const float4 va = *(const float4*)(Vp + nb + lcol);
        const float4 vb = *(const float4*)(Vp + nb + lcol + 4);
        float ss = va.x*va.x + va.y*va.y + va.z*va.z + va.w*va.w
                 + vb.x*vb.x + vb.y*vb.y + vb.z*vb.z + vb.w*vb.w;
        ss += __shfl_xor_sync(0xffffffffu, ss, 1);
        ss += __shfl_xor_sync(0xffffffffu, ss, 2);
        ss += __shfl_xor_sync(0xffffffffu, ss, 4);
        const float denom = fmaxf(fmaf(k, ss, 1.f), 1e-15f);
        const float rinv  = 1.f / denom;

        const float4 qa = *(const float4*)(Qp + nb + lcol);
        const float4 qb = *(const float4*)(Qp + nb + lcol + 4);
        float v1v[8];
        v1v[0] = elu1(qa.x*rinv); v1v[1] = elu1(qa.y*rinv);
        v1v[2] = elu1(qa.z*rinv); v1v[3] = elu1(qa.w*rinv);
        v1v[4] = elu1(qb.x*rinv); v1v[5] = elu1(qb.y*rinv);
        v1v[6] = elu1(qb.z*rinv); v1v[7] = elu1(qb.w*rinv);

        float dp = v1v[0]*vs_s[lcol+0] + v1v[1]*vs_s[lcol+1]
                 + v1v[2]*vs_s[lcol+2] + v1v[3]*vs_s[lcol+3]
                 + v1v[4]*vs_s[lcol+4] + v1v[5]*vs_s[lcol+5]
                 + v1v[6]*vs_s[lcol+6] + v1v[7]*vs_s[lcol+7];
        dp += __shfl_xor_sync(0xffffffffu, dp, 1);
        dp += __shfl_xor_sync(0xffffffffu, dp, 2);
        dp += __shfl_xor_sync(0xffffffffu, dp, 4);

        *(float4*)&v1_s[lrow][lcol]     = make_float4(v1v[0], v1v[1], v1v[2], v1v[3]);
        *(float4*)&v1_s[lrow][lcol + 4] = make_float4(v1v[4], v1v[5], v1v[6], v1v[7]);
        __syncwarp();

        // --- GEMV: X[e] = sum_d v1[d] * ctx[d][e], thread owns 8 e's ---
        u64t X01 = pk2(0.f,0.f), X23 = pk2(0.f,0.f), X45 = pk2(0.f,0.f), X67 = pk2(0.f,0.f);
        #pragma unroll
        for (int d4 = 0; d4 < DH; d4 += 4) {
            const float4 a4 = *(const float4*)&v1_s[lrow][d4];
            #pragma unroll
            for (int j = 0; j < 4; j++) {
                const float a = (j == 0) ? a4.x : (j == 1) ? a4.y : (j == 2) ? a4.z : a4.w;
                const int d = d4 + j;
                const float4 b0 = *(const float4*)&ctx_s[d][lcol];
                const float4 b1 = *(const float4*)&ctx_s[d][lcol + 4];
                const u64t aa = pk2(a, a);
                fma2(X01, aa, pk2(b0.x, b0.y));
                fma2(X23, aa, pk2(b0.z, b0.w));
                fma2(X45, aa, pk2(b1.x, b1.y));
                fma2(X67, aa, pk2(b1.z, b1.w));
            }
        }
        __syncwarp();

        float x[8];
        upk2(X01, x[0], x[1]); upk2(X23, x[2], x[3]);
        upk2(X45, x[4], x[5]); upk2(X67, x[6], x[7]);

        const float Dinv = 1.f / ((dp == 0.f) ? 1e-5f : dp);
        float n2 = 0.f;
        #pragma unroll
        for (int j = 0; j < 8; j++) { x[j] *= Dinv; n2 += x[j] * x[j]; }
        n2 += __shfl_xor_sync(0xffffffffu, n2, 1);
        n2 += __shfl_xor_sync(0xffffffffu, n2, 2);
        n2 += __shfl_xor_sync(0xffffffffu, n2, 4);

        // project 1
        const float norm = fmaxf(sqrtf(n2), 1e-15f);
        const float scl  = (norm > maxnorm) ? (maxnorm / norm) : 1.f;
        // mobius scalar mul (r = 0.5)
        const float xn = fmaxf(norm * scl, 1e-15f);
        float tk;
        if (hyp) {
            const float u_ = atanhf(fminf(sk * xn, 1.f - 1e-7f));   // = sk * artan_k
            tk = tanhf(0.5f * u_) / sk;
        } else {
            const float u_ = atanf(sk * xn);
            tk = tanf(0.5f * u_) / sk;
        }
        const float s2 = tk / xn;
        // project 2 (new norm is |tk|)
        const float nrm2 = fmaxf(fabsf(tk), 1e-15f);
        const float scl2 = (nrm2 > maxnorm) ? (maxnorm / nrm2) : 1.f;
        const float st = scl * s2 * scl2;

        *(float4*)(Op + nb + lcol)     = make_float4(x[0]*st, x[1]*st, x[2]*st, x[3]*st);
        *(float4*)(Op + nb + lcol + 4) = make_float4(x[4]*st, x[5]*st, x[6]*st, x[7]*st);
    }
}

extern "C" void kernel_launch(void* const* d_in, const int* in_sizes, int n_in,
                              void* d_out, int out_size)
{
    const float* Q    = (const float*)d_in[0];
    const float* K    = (const float*)d_in[1];
    const float* V    = (const float*)d_in[2];
    const float* mask = (const float*)d_in[3];
    const float* c    = (const float*)d_in[4];
    const int csize = in_sizes[4];
    const int N     = in_sizes[3];
    const int BH    = in_sizes[0] / (N * DH);

    const int nctx = BH * DH * DH;
    const int nvs  = BH * DH;

    int splits = 8;
    while (splits > 1 && (N % (splits * 32) != 0)) splits >>= 1;

    zero_kernel<<<(nctx + 255) / 256, 256>>>(nctx, nvs);
    dim3 grid(splits, BH);
    ctx_kernel<<<grid, 256>>>(K, V, mask, c, csize, N);
    out_kernel<<<grid, 256>>>(Q, V, c, csize, N, (float*)d_out);
}

// round 3
// speedup vs baseline: 1.6897x; 1.6897x over previous
#include <cuda_runtime.h>

#define DH 64
#define MAX_BH 128
#define MAX_N 8192
#define NSPLIT 8

// ---- scratch (static __device__: no allocation) ----
__device__ float g_ctxp[NSPLIT * MAX_BH * DH * DH];  // per-split ctx partials
__device__ float g_vsump[NSPLIT * MAX_BH * DH];      // per-split vsum partials
__device__ float g_ctxr[MAX_BH * DH * DH];           // reduced ctx
__device__ float g_vsumr[MAX_BH * DH];               // reduced vsum
__device__ float g_rinv[MAX_BH * MAX_N];             // per-row 1/denom (from V)

typedef unsigned long long u64t;

__device__ __forceinline__ u64t pk2(float lo, float hi) {
    u64t r; asm("mov.b64 %0, {%1, %2};" : "=l"(r) : "f"(lo), "f"(hi)); return r;
}
__device__ __forceinline__ void upk2(u64t v, float& lo, float& hi) {
    asm("mov.b64 {%0, %1}, %2;" : "=f"(lo), "=f"(hi) : "l"(v));
}
__device__ __forceinline__ void fma2(u64t& acc, u64t a, u64t b) {
    asm("fma.rn.f32x2 %0, %1, %2, %0;" : "+l"(acc) : "l"(a), "l"(b));
}
__device__ __forceinline__ float elu1(float v) { return v > 0.f ? v + 1.f : __expf(v); }

// ===========================================================================
// K1: ctx[d][e] = sum_n v2[n,d]*x[n,e], vsum[d] = sum_n v2[n,d]; also stash rinv.
// Grid (splits, BH), 256 threads. 32-row tiles. Warp-pair p handles t in [8p,8p+8);
// warp lo/hi of pair handles d-half. Thread computes an 8x8 ctx tile.
// v2 stored DUPLICATED (a-operand loads dup pairs as u64 directly),
// x stored raw (b-operand loads e-pairs as u64 directly). Group padding
// (20-float / 12-float strides) keeps broadcast loads conflict-free.
// ===========================================================================
__global__ void __launch_bounds__(256, 2)
ctx_kernel(const float* __restrict__ Kg, const float* __restrict__ Vg,
           const float* __restrict__ mask, const float* __restrict__ c,
           int csize, int N)
{
    const int split = blockIdx.x, bh = blockIdx.y;
    const int rows  = N / gridDim.x;
    const int n0    = split * rows;
    const float k   = (csize > 1) ? c[bh % csize] : c[0];

    __shared__ float v2d[32 * 160];   // dup v2: per 8-d group: 16 dup floats + 4 pad
    __shared__ float x_s[32 * 96];    // raw x : per 8-e group:  8 floats + 4 pad

    const int tid   = threadIdx.x;
    const int lrow  = tid >> 3;
    const int lcol8 = tid & 7;
    const int wid   = tid >> 5, lane = tid & 31;
    const int pairid = wid >> 1, dhalf = wid & 1;
    const int dgrp = lane >> 3, egrp = lane & 7;
    const int gd   = dhalf * 4 + dgrp;

    const float* Kp = Kg + (size_t)bh * N * DH;
    const float* Vp = Vg + (size_t)bh * N * DH;

    u64t acc[8][4] = {};
    float vsum[8] = {0.f,0.f,0.f,0.f,0.f,0.f,0.f,0.f};

    for (int t0 = 0; t0 < rows; t0 += 32) {
        const int n = n0 + t0 + lrow;
        const size_t nb = (size_t)n * DH + lcol8 * 8;

        // ---- elementwise (8 lanes per row) ----
        const float4 va = *(const float4*)(Vp + nb);
        const float4 vb = *(const float4*)(Vp + nb + 4);
        float ss = va.x*va.x + va.y*va.y + va.z*va.z + va.w*va.w
                 + vb.x*vb.x + vb.y*vb.y + vb.z*vb.z + vb.w*vb.w;
        ss += __shfl_xor_sync(0xffffffffu, ss, 1);
        ss += __shfl_xor_sync(0xffffffffu, ss, 2);
        ss += __shfl_xor_sync(0xffffffffu, ss, 4);
        const float denom = fmaxf(fmaf(k, ss, 1.f), 1e-15f);
        const float rinv  = 1.f / denom;
        const float g     = 2.f * rinv;
        const float gm1   = g - 1.f;
        const float sgn   = (gm1 >= 0.f) ? 1.f : -1.f;
        const float d2    = sgn * fmaxf(fabsf(gm1), 1e-10f);
        const float m     = mask[n];
        const float xs    = g / d2 * m;
        const float d2m   = d2 * m;

        float* xw = &x_s[lrow * 96 + lcol8 * 12];
        *(float4*)(xw)     = make_float4(va.x*xs, va.y*xs, va.z*xs, va.w*xs);
        *(float4*)(xw + 4) = make_float4(vb.x*xs, vb.y*xs, vb.z*xs, vb.w*xs);

        const float4 ka = *(const float4*)(Kp + nb);
        const float4 kb = *(const float4*)(Kp + nb + 4);
        float w[8];
        w[0] = d2m*elu1(ka.x*rinv); w[1] = d2m*elu1(ka.y*rinv);
        w[2] = d2m*elu1(ka.z*rinv); w[3] = d2m*elu1(ka.w*rinv);
        w[4] = d2m*elu1(kb.x*rinv); w[5] = d2m*elu1(kb.y*rinv);
        w[6] = d2m*elu1(kb.z*rinv); w[7] = d2m*elu1(kb.w*rinv);
        float* vw = &v2d[lrow * 160 + lcol8 * 20];
        *(float4*)(vw)      = make_float4(w[0], w[0], w[1], w[1]);
        *(float4*)(vw + 4)  = make_float4(w[2], w[2], w[3], w[3]);
        *(float4*)(vw + 8)  = make_float4(w[4], w[4], w[5], w[5]);
        *(float4*)(vw + 12) = make_float4(w[6], w[6], w[7], w[7]);
        #pragma unroll
        for (int j = 0; j < 8; j++) vsum[j] += w[j];

        if (lcol8 == 0) g_rinv[(size_t)bh * N + n] = rinv;
        __syncthreads();

        // ---- GEMM: 8 rank-1 updates per warp-pair, 8x8 per thread ----
        #pragma unroll
        for (int t = 0; t < 8; t++) {
            const int tt = pairid * 8 + t;
            const ulonglong2* ap = (const ulonglong2*)&v2d[tt * 160 + gd * 20];
            const ulonglong2 a01 = ap[0], a23 = ap[1], a45 = ap[2], a67 = ap[3];
            const ulonglong2* bp = (const ulonglong2*)&x_s[tt * 96 + egrp * 12];
            const ulonglong2 b03 = bp[0], b47 = bp[1];
            const u64t A[8] = {a01.x, a01.y, a23.x, a23.y, a45.x, a45.y, a67.x, a67.y};
            const u64t B[4] = {b03.x, b03.y, b47.x, b47.y};
            #pragma unroll
            for (int dd = 0; dd < 8; dd++) {
                fma2(acc[dd][0], A[dd], B[0]);
                fma2(acc[dd][1], A[dd], B[1]);
                fma2(acc[dd][2], A[dd], B[2]);
                fma2(acc[dd][3], A[dd], B[3]);
            }
        }
        __syncthreads();
    }

    // ---- reduce the 4 warp-pair copies via smem, then write split partial ----
    float* red = v2d;   // 4096 floats needed; v2d has 5120
    #pragma unroll
    for (int p = 0; p < 4; p++) {
        if (pairid == p) {
            #pragma unroll
            for (int dd = 0; dd < 8; dd++) {
                #pragma unroll
                for (int ee = 0; ee < 4; ee++) {
                    float f0, f1; upk2(acc[dd][ee], f0, f1);
                    const int idx = (gd * 8 + dd) * 64 + egrp * 8 + ee * 2;
                    if (p == 0) { red[idx] = f0; red[idx + 1] = f1; }
                    else        { red[idx] += f0; red[idx + 1] += f1; }
                }
            }
        }
        __syncthreads();
    }
    float* dst = g_ctxp + ((size_t)bh * NSPLIT + split) * (DH * DH);
    for (int i = tid; i < DH * DH; i += 256) dst[i] = red[i];

    // ---- vsum partial ----
    float* vb2 = x_s;   // 2048 floats needed
    #pragma unroll
    for (int j = 0; j < 8; j++) vb2[lrow * 64 + lcol8 * 8 + j] = vsum[j];
    __syncthreads();
    if (tid < DH) {
        float s = 0.f;
        #pragma unroll
        for (int r = 0; r < 32; r++) s += vb2[r * 64 + tid];
        g_vsump[((size_t)bh * NSPLIT + split) * DH + tid] = s;
    }
}

// ===========================================================================
// K1b: reduce split partials. Grid = BH blocks x 256 threads.
// ===========================================================================
__global__ void __launch_bounds__(256)
reduce_kernel(int splits)
{
    const int bh = blockIdx.x, tid = threadIdx.x;
    for (int i = tid; i < DH * DH; i += 256) {
        float s = 0.f;
        for (int p = 0; p < splits; p++)
            s += g_ctxp[((size_t)bh * NSPLIT + p) * (DH * DH) + i];
        g_ctxr[(size_t)bh * DH * DH + i] = s;
    }
    if (tid < DH) {
        float s = 0.f;
        for (int p = 0; p < splits; p++)
            s += g_vsump[((size_t)bh * NSPLIT + p) * DH + tid];
        g_vsumr[bh * DH + tid] = s;
    }
}

// ===========================================================================
// K2: per row X = (v1 @ ctx)/(v1 . vsum), then project -> mobius(0.5) -> project.
// v1 stored DUPLICATED, row stride 140 with stagger ((row>>2)&3)*4:
// max in-row extent = 12 + 128 = 140 -> NO row overlap (round-2 bug fixed),
// and the stagger decorrelates banks for the 4-rows-apart a-operand loads.
// ===========================================================================
#define V1STRIDE 140
#define V1DUP_ADDR(row, col2) ((row) * V1STRIDE + (((row) >> 2) & 3) * 4 + (col2))
#define K2_SMEM_FLOATS (DH * 96 + 128 * V1STRIDE + 128 + 64)

__global__ void __launch_bounds__(256)
out_kernel(const float* __restrict__ Qg, const float* __restrict__ c,
           int csize, int N, float* __restrict__ out)
{
    extern __shared__ float smem[];
    float* ctx_s = smem;                        // 64*96 = 6144
    float* v1d   = smem + DH * 96;              // 128*140 = 17920
    float* dpbuf = v1d + 128 * V1STRIDE;        // 128
    float* vs_s  = dpbuf + 128;                 // 64

    const int chunk = blockIdx.x, bh = blockIdx.y;
    const int rows  = N / gridDim.x;
    const int n0    = chunk * rows;
    const float k   = (csize > 1) ? c[bh % csize] : c[0];
    const float sk  = sqrtf(fabsf(k) + 1e-15f);
    const float maxnorm = (k < 0.f) ? (1.f - 0.004f) / sk : 1e15f;
    const bool  hyp = (k < 0.f);

    const int tid   = threadIdx.x;
    const int lrow  = tid >> 3, lcol8 = tid & 7;
    const int wid   = tid >> 5, lane = tid & 31;
    const int rgrp  = lane >> 3, egrp = lane & 7;
    const int e0    = egrp * 8;

    // ---- prologue ----
    const float* ctxg = g_ctxr + (size_t)bh * DH * DH;
    for (int i = tid; i < DH * DH; i += 256) {
        const int d = i >> 6, e = i & 63;
        ctx_s[d * 96 + (e >> 3) * 12 + (e & 7)] = ctxg[i];
    }
    if (tid < DH) vs_s[tid] = g_vsumr[bh * DH + tid];
    __syncthreads();

    const float* Qp = Qg + (size_t)bh * N * DH;
    const float* rv = g_rinv + (size_t)bh * N;
    float*       Op = out + (size_t)bh * N * DH;

    const int nIter = rows / 128;
    for (int it = 0; it < nIter; it++) {
        const int base = n0 + it * 128;

        // ---- elementwise: v1 = elu(Q*rinv)+1 (dup into smem), dp = v1.vsum ----
        #pragma unroll
        for (int s = 0; s < 4; s++) {
            const int lr = s * 32 + lrow;
            const int n  = base + lr;
            const float rinv = rv[n];
            const size_t nb = (size_t)n * DH + lcol8 * 8;
            const float4 qa = *(const float4*)(Qp + nb);
            const float4 qb = *(const float4*)(Qp + nb + 4);
            float v1v[8];
            v1v[0] = elu1(qa.x*rinv); v1v[1] = elu1(qa.y*rinv);
            v1v[2] = elu1(qa.z*rinv); v1v[3] = elu1(qa.w*rinv);
            v1v[4] = elu1(qb.x*rinv); v1v[5] = elu1(qb.y*rinv);
            v1v[6] = elu1(qb.z*rinv); v1v[7] = elu1(qb.w*rinv);

            const int vc = lcol8 * 8;
            float dp = v1v[0]*vs_s[vc+0] + v1v[1]*vs_s[vc+1]
                     + v1v[2]*vs_s[vc+2] + v1v[3]*vs_s[vc+3]
                     + v1v[4]*vs_s[vc+4] + v1v[5]*vs_s[vc+5]
                     + v1v[6]*vs_s[vc+6] + v1v[7]*vs_s[vc+7];
            dp += __shfl_xor_sync(0xffffffffu, dp, 1);
            dp += __shfl_xor_sync(0xffffffffu, dp, 2);
            dp += __shfl_xor_sync(0xffffffffu, dp, 4);

            float* vw = &v1d[V1DUP_ADDR(lr, 2 * vc)];
            *(float4*)(vw)      = make_float4(v1v[0], v1v[0], v1v[1], v1v[1]);
            *(float4*)(vw + 4)  = make_float4(v1v[2], v1v[2], v1v[3], v1v[3]);
            *(float4*)(vw + 8)  = make_float4(v1v[4], v1v[4], v1v[5], v1v[5]);
            *(float4*)(vw + 12) = make_float4(v1v[6], v1v[6], v1v[7], v1v[7]);
            if (lcol8 == 0) dpbuf[lr] = dp;
        }
        __syncthreads();

        // ---- GEMV: thread = 4 rows x 8 e ----
        const int row0 = wid * 16 + rgrp * 4;
        int abase[4];
        #pragma unroll
        for (int rr = 0; rr < 4; rr++) abase[rr] = V1DUP_ADDR(row0 + rr, 0);

        u64t acc[4][4] = {};
        #pragma unroll
        for (int d = 0; d < DH; d += 2) {
            const ulonglong2* bp0 = (const ulonglong2*)&ctx_s[d * 96 + egrp * 12];
            const ulonglong2* bp1 = (const ulonglong2*)&ctx_s[(d + 1) * 96 + egrp * 12];
            const ulonglong2 bA = bp0[0], bB = bp0[1];
            const ulonglong2 cA = bp1[0], cB = bp1[1];
            #pragma unroll
            for (int rr = 0; rr < 4; rr++) {
                const ulonglong2 a = *(const ulonglong2*)&v1d[abase[rr] + 2 * d];
                fma2(acc[rr][0], a.x, bA.x);
                fma2(acc[rr][1], a.x, bA.y);
                fma2(acc[rr][2], a.x, bB.x);
                fma2(acc[rr][3], a.x, bB.y);
                fma2(acc[rr][0], a.y, cA.x);
                fma2(acc[rr][1], a.y, cA.y);
                fma2(acc[rr][2], a.y, cB.x);
                fma2(acc[rr][3], a.y, cB.y);
            }
        }

        // ---- tail: Dinv scale, project -> mobius(0.5) -> project, store ----
        #pragma unroll
        for (int rr = 0; rr < 4; rr++) {
            const int lr = row0 + rr;
            const int n  = base + lr;
            float x[8];
            upk2(acc[rr][0], x[0], x[1]); upk2(acc[rr][1], x[2], x[3]);
            upk2(acc[rr][2], x[4], x[5]); upk2(acc[rr][3], x[6], x[7]);

            const float dp = dpbuf[lr];
            const float Dinv = 1.f / ((dp == 0.f) ? 1e-5f : dp);
            float n2 = 0.f;
            #pragma unroll
            for (int j = 0; j < 8; j++) { x[j] *= Dinv; n2 += x[j] * x[j]; }
            n2 += __shfl_xor_sync(0xffffffffu, n2, 1);
            n2 += __shfl_xor_sync(0xffffffffu, n2, 2);
            n2 += __shfl_xor_sync(0xffffffffu, n2, 4);

            const float norm = fmaxf(sqrtf(n2), 1e-15f);
            const float scl  = (norm > maxnorm) ? (maxnorm / norm) : 1.f;
            const float xn   = fmaxf(norm * scl, 1e-15f);
            float tk;
            if (hyp) {
                const float u_ = atanhf(fminf(sk * xn, 1.f - 1e-7f));
                tk = tanhf(0.5f * u_) / sk;
            } else {
                const float u_ = atanf(sk * xn);
                tk = tanf(0.5f * u_) / sk;
            }
            const float s2   = tk / xn;
            const float nrm2 = fmaxf(fabsf(tk), 1e-15f);
            const float scl2 = (nrm2 > maxnorm) ? (maxnorm / nrm2) : 1.f;
            const float st   = scl * s2 * scl2;

            float* o = Op + (size_t)n * DH + e0;
            *(float4*)(o)     = make_float4(x[0]*st, x[1]*st, x[2]*st, x[3]*st);
            *(float4*)(o + 4) = make_float4(x[4]*st, x[5]*st, x[6]*st, x[7]*st);
        }
        __syncthreads();
    }
}

extern "C" void kernel_launch(void* const* d_in, const int* in_sizes, int n_in,
                              void* d_out, int out_size)
{
    const float* Q    = (const float*)d_in[0];
    const float* K    = (const float*)d_in[1];
    const float* V    = (const float*)d_in[2];
    const float* mask = (const float*)d_in[3];
    const float* c    = (const float*)d_in[4];
    const int csize = in_sizes[4];
    const int N     = in_sizes[3];
    const int BH    = in_sizes[0] / (N * DH);

    int splits = NSPLIT;
    while (splits > 1 && (N % (splits * 32) != 0)) splits >>= 1;
    int chunks = NSPLIT;
    while (chunks > 1 && (N % (chunks * 128) != 0)) chunks >>= 1;

    cudaFuncSetAttribute(out_kernel, cudaFuncAttributeMaxDynamicSharedMemorySize,
                         K2_SMEM_FLOATS * sizeof(float));

    dim3 g1(splits, BH);
    ctx_kernel<<<g1, 256>>>(K, V, mask, c, csize, N);
    reduce_kernel<<<BH, 256>>>(splits);
    dim3 g2(chunks, BH);
    out_kernel<<<g2, 256, K2_SMEM_FLOATS * sizeof(float)>>>(Q, c, csize, N, (float*)d_out);
}

// round 4
// speedup vs baseline: 1.7012x; 1.0068x over previous
#include <cuda_runtime.h>

#define DH 64
#define MAX_BH 128
#define MAX_N 8192
#define NSPLIT 8

// ---- scratch (static __device__: no allocation) ----
__device__ float g_ctxp[NSPLIT * MAX_BH * DH * DH];  // per-split ctx partials
__device__ float g_vsump[NSPLIT * MAX_BH * DH];      // per-split vsum partials
__device__ float g_rinv[MAX_BH * MAX_N];             // per-row 1/denom (from V)

typedef unsigned long long u64t;

__device__ __forceinline__ u64t pk2(float lo, float hi) {
    u64t r; asm("mov.b64 %0, {%1, %2};" : "=l"(r) : "f"(lo), "f"(hi)); return r;
}
__device__ __forceinline__ void upk2(u64t v, float& lo, float& hi) {
    asm("mov.b64 {%0, %1}, %2;" : "=f"(lo), "=f"(hi) : "l"(v));
}
__device__ __forceinline__ void fma2(u64t& acc, u64t a, u64t b) {
    asm("fma.rn.f32x2 %0, %1, %2, %0;" : "+l"(acc) : "l"(a), "l"(b));
}
__device__ __forceinline__ float elu1(float v) { return v > 0.f ? v + 1.f : __expf(v); }

__device__ __forceinline__ unsigned smem_u32(const void* p) {
    return (unsigned)__cvta_generic_to_shared(p);
}
__device__ __forceinline__ void cp16(unsigned s, const float* g) {
    asm volatile("cp.async.cg.shared.global [%0], [%1], 16;" :: "r"(s), "l"(g));
}
#define CP_COMMIT() asm volatile("cp.async.commit_group;" ::: "memory")
#define CP_WAIT(n)  asm volatile("cp.async.wait_group %0;" :: "n"(n) : "memory")

// ===========================================================================
// K1: ctx[d][e] = sum_n v2[n,d]*x[n,e], vsum[d] = sum_n v2[n,d]; stash rinv.
// cp.async double-buffered staging of K/V/mask hides global latency under the
// GEMM phase. 32-row tiles, 8x8 thread tiles, dup/padded smem layouts.
// ===========================================================================
#define K1_STV   0            // 2*32*68 = 4352 floats (V stage, 2 bufs)
#define K1_STK   4352         // 4352 (K stage)
#define K1_STM   8704         // 2*32 = 64 (mask stage)
#define K1_V2D   8768         // 32*160 = 5120 (dup v2)
#define K1_XS    13888        // 32*96 = 3072 (raw x)
#define K1_FLOATS 16960       // 67840 bytes

__global__ void __launch_bounds__(256, 2)
ctx_kernel(const float* __restrict__ Kg, const float* __restrict__ Vg,
           const float* __restrict__ mask, const float* __restrict__ c,
           int csize, int N)
{
    extern __shared__ float sm[];
    float* stV = sm + K1_STV;
    float* stK = sm + K1_STK;
    float* stM = sm + K1_STM;
    float* v2d = sm + K1_V2D;
    float* x_s = sm + K1_XS;

    const int split = blockIdx.x, bh = blockIdx.y;
    const int rows  = N / gridDim.x;
    const int n0    = split * rows;
    const float k   = (csize > 1) ? c[bh % csize] : c[0];

    const int tid   = threadIdx.x;
    const int lrow  = tid >> 3;
    const int lcol8 = tid & 7;
    const int wid   = tid >> 5, lane = tid & 31;
    const int pairid = wid >> 1, dhalf = wid & 1;
    const int dgrp = lane >> 3, egrp = lane & 7;
    const int gd   = dhalf * 4 + dgrp;

    const float* Kp = Kg + (size_t)bh * N * DH;
    const float* Vp = Vg + (size_t)bh * N * DH;

    const int pr_r0  = tid >> 4;            // 0..15
    const int pr_off = (tid & 15) * 4;      // 0..60

    auto prefetch = [&](int t0, int p) {
        const float* gv = Vp + (size_t)(n0 + t0) * DH;
        const float* gk = Kp + (size_t)(n0 + t0) * DH;
        const unsigned sv = smem_u32(stV + p * 2176);
        const unsigned sk = smem_u32(stK + p * 2176);
        cp16(sv + (pr_r0 * 68 + pr_off) * 4,        gv + pr_r0 * DH + pr_off);
        cp16(sv + ((pr_r0 + 16) * 68 + pr_off) * 4, gv + (pr_r0 + 16) * DH + pr_off);
        cp16(sk + (pr_r0 * 68 + pr_off) * 4,        gk + pr_r0 * DH + pr_off);
        cp16(sk + ((pr_r0 + 16) * 68 + pr_off) * 4, gk + (pr_r0 + 16) * DH + pr_off);
        if (tid < 8) cp16(smem_u32(stM + p * 32) + tid * 16, mask + n0 + t0 + tid * 4);
    };

    u64t acc[8][4] = {};
    float vsum[8] = {0.f,0.f,0.f,0.f,0.f,0.f,0.f,0.f};

    const int T = rows / 32;
    prefetch(0, 0);
    CP_COMMIT();

    for (int t = 0; t < T; t++) {
        const int p = t & 1;
        if (t + 1 < T) { prefetch((t + 1) * 32, p ^ 1); CP_COMMIT(); CP_WAIT(1); }
        else           { CP_WAIT(0); }
        __syncthreads();   // stage[p] visible to all; prior GEMM done with v2d/x_s

        // ---- elementwise from stage ----
        const int n = n0 + t * 32 + lrow;
        const float* vr = stV + p * 2176 + lrow * 68 + lcol8 * 8;
        const float4 va = *(const float4*)vr;
        const float4 vb = *(const float4*)(vr + 4);
        float ss = va.x*va.x + va.y*va.y + va.z*va.z + va.w*va.w
                 + vb.x*vb.x + vb.y*vb.y + vb.z*vb.z + vb.w*vb.w;
        ss += __shfl_xor_sync(0xffffffffu, ss, 1);
        ss += __shfl_xor_sync(0xffffffffu, ss, 2);
        ss += __shfl_xor_sync(0xffffffffu, ss, 4);
        const float denom = fmaxf(fmaf(k, ss, 1.f), 1e-15f);
        const float rinv  = 1.f / denom;
        const float g     = 2.f * rinv;
        const float gm1   = g - 1.f;
        const float sgn   = (gm1 >= 0.f) ? 1.f : -1.f;
        const float d2    = sgn * fmaxf(fabsf(gm1), 1e-10f);
        const float m     = stM[p * 32 + lrow];
        const float xs    = g / d2 * m;
        const float d2m   = d2 * m;

        float* xw = &x_s[lrow * 96 + lcol8 * 12];
        *(float4*)(xw)     = make_float4(va.x*xs, va.y*xs, va.z*xs, va.w*xs);
        *(float4*)(xw + 4) = make_float4(vb.x*xs, vb.y*xs, vb.z*xs, vb.w*xs);

        const float* kr = stK + p * 2176 + lrow * 68 + lcol8 * 8;
        const float4 ka = *(const float4*)kr;
        const float4 kb = *(const float4*)(kr + 4);
        float w[8];
        w[0] = d2m*elu1(ka.x*rinv); w[1] = d2m*elu1(ka.y*rinv);
        w[2] = d2m*elu1(ka.z*rinv); w[3] = d2m*elu1(ka.w*rinv);
        w[4] = d2m*elu1(kb.x*rinv); w[5] = d2m*elu1(kb.y*rinv);
        w[6] = d2m*elu1(kb.z*rinv); w[7] = d2m*elu1(kb.w*rinv);
        float* vw = &v2d[lrow * 160 + lcol8 * 20];
        *(float4*)(vw)      = make_float4(w[0], w[0], w[1], w[1]);
        *(float4*)(vw + 4)  = make_float4(w[2], w[2], w[3], w[3]);
        *(float4*)(vw + 8)  = make_float4(w[4], w[4], w[5], w[5]);
        *(float4*)(vw + 12) = make_float4(w[6], w[6], w[7], w[7]);
        #pragma unroll
        for (int j = 0; j < 8; j++) vsum[j] += w[j];

        if (lcol8 == 0) g_rinv[(size_t)bh * N + n] = rinv;
        __syncthreads();

        // ---- GEMM: 8 rank-1 updates per warp-pair, 8x8 per thread ----
        #pragma unroll
        for (int tt8 = 0; tt8 < 8; tt8++) {
            const int tt = pairid * 8 + tt8;
            const ulonglong2* ap = (const ulonglong2*)&v2d[tt * 160 + gd * 20];
            const ulonglong2 a01 = ap[0], a23 = ap[1], a45 = ap[2], a67 = ap[3];
            const ulonglong2* bp = (const ulonglong2*)&x_s[tt * 96 + egrp * 12];
            const ulonglong2 b03 = bp[0], b47 = bp[1];
            const u64t A[8] = {a01.x, a01.y, a23.x, a23.y, a45.x, a45.y, a67.x, a67.y};
            const u64t B[4] = {b03.x, b03.y, b47.x, b47.y};
            #pragma unroll
            for (int dd = 0; dd < 8; dd++) {
                fma2(acc[dd][0], A[dd], B[0]);
                fma2(acc[dd][1], A[dd], B[1]);
                fma2(acc[dd][2], A[dd], B[2]);
                fma2(acc[dd][3], A[dd], B[3]);
            }
        }
    }
    __syncthreads();   // GEMM done before epilogue reuses v2d/x_s

    // ---- reduce the 4 warp-pair copies via smem, write split partial ----
    float* red = v2d;   // 4096 floats needed; v2d has 5120
    #pragma unroll
    for (int p = 0; p < 4; p++) {
        if (pairid == p) {
            #pragma unroll
            for (int dd = 0; dd < 8; dd++) {
                #pragma unroll
                for (int ee = 0; ee < 4; ee++) {
                    float f0, f1; upk2(acc[dd][ee], f0, f1);
                    const int idx = (gd * 8 + dd) * 64 + egrp * 8 + ee * 2;
                    if (p == 0) { red[idx] = f0; red[idx + 1] = f1; }
                    else        { red[idx] += f0; red[idx + 1] += f1; }
                }
            }
        }
        __syncthreads();
    }
    float* dst = g_ctxp + ((size_t)bh * NSPLIT + split) * (DH * DH);
    for (int i = tid; i < DH * DH; i += 256) dst[i] = red[i];

    // ---- vsum partial ----
    float* vb2 = x_s;
    #pragma unroll
    for (int j = 0; j < 8; j++) vb2[lrow * 64 + lcol8 * 8 + j] = vsum[j];
    __syncthreads();
    if (tid < DH) {
        float s = 0.f;
        #pragma unroll
        for (int r = 0; r < 32; r++) s += vb2[r * 64 + tid];
        g_vsump[((size_t)bh * NSPLIT + split) * DH + tid] = s;
    }
}

// ===========================================================================
// K2: fused split-reduce prologue + per-row X = (v1@ctx)/(v1.vsum) + geometry.
// 64-row iterations; cp.async double-buffered Q + rinv staging; dup v1
// (stride 140 + stagger, no overlap); group-padded ctx.
// ===========================================================================
#define V1STRIDE 140
#define V1DUP_ADDR(row, col2) ((row) * V1STRIDE + (((row) >> 2) & 3) * 4 + (col2))
#define K2_CTX  0                 // 64*96  = 6144
#define K2_V1D  6144              // 64*140 = 8960
#define K2_STQ  15104             // 2*64*68 = 8704
#define K2_STR  23808             // 2*64 = 128
#define K2_DP   23936             // 64
#define K2_VS   24000             // 64
#define K2_FLOATS 24064           // 96256 bytes

__global__ void __launch_bounds__(256, 2)
out_kernel(const float* __restrict__ Qg, const float* __restrict__ c,
           int csize, int N, int splits, float* __restrict__ out)
{
    extern __shared__ float sm[];
    float* ctx_s = sm + K2_CTX;
    float* v1d   = sm + K2_V1D;
    float* stQ   = sm + K2_STQ;
    float* strv  = sm + K2_STR;
    float* dpbuf = sm + K2_DP;
    float* vs_s  = sm + K2_VS;

    const int chunk = blockIdx.x, bh = blockIdx.y;
    const int rows  = N / gridDim.x;
    const int n0    = chunk * rows;
    const float k   = (csize > 1) ? c[bh % csize] : c[0];
    const float sk  = sqrtf(fabsf(k) + 1e-15f);
    const float maxnorm = (k < 0.f) ? (1.f - 0.004f) / sk : 1e15f;
    const bool  hyp = (k < 0.f);

    const int tid   = threadIdx.x;
    const int lrow  = tid >> 3, lcol8 = tid & 7;
    const int wid   = tid >> 5, lane = tid & 31;
    const int rgrp  = lane >> 3, egrp = lane & 7;
    const int e0    = egrp * 8;

    const float* Qp = Qg + (size_t)bh * N * DH;
    const float* rv = g_rinv + (size_t)bh * N;
    float*       Op = out + (size_t)bh * N * DH;

    auto prefetchQ = [&](int b0, int p) {
        const float* gq = Qp + (size_t)b0 * DH;
        const unsigned sq = smem_u32(stQ + p * 4352);
        #pragma unroll
        for (int kk = 0; kk < 4; kk++) {
            const int ch = tid + kk * 256;
            const int r = ch >> 4, off = (ch & 15) * 4;
            cp16(sq + (r * 68 + off) * 4, gq + r * DH + off);
        }
        if (tid < 16) cp16(smem_u32(strv + p * 64) + tid * 16, rv + b0 + tid * 4);
    };

    // kick the first stage before the (L2-bound) reduce prologue
    prefetchQ(n0, 0);
    CP_COMMIT();

    // ---- fused reduce of K1 split partials ----
    const float* bctx = g_ctxp + (size_t)bh * NSPLIT * DH * DH;
    for (int i = tid; i < DH * DH; i += 256) {
        float s = 0.f;
        for (int p = 0; p < splits; p++) s += bctx[p * DH * DH + i];
        const int d = i >> 6, e = i & 63;
        ctx_s[d * 96 + (e >> 3) * 12 + (e & 7)] = s;
    }
    if (tid < DH) {
        float s = 0.f;
        for (int p = 0; p < splits; p++) s += g_vsump[((size_t)bh * NSPLIT + p) * DH + tid];
        vs_s[tid] = s;
    }

    const int nIter = rows / 64;
    for (int it = 0; it < nIter; it++) {
        const int p = it & 1;
        if (it + 1 < nIter) { prefetchQ(n0 + (it + 1) * 64, p ^ 1); CP_COMMIT(); CP_WAIT(1); }
        else                { CP_WAIT(0); }
        __syncthreads();   // stage ready; prior GEMV done with v1d/dpbuf; prologue done

        // ---- elementwise: v1 = elu(Q*rinv)+1 (dup), dp = v1.vsum ----
        #pragma unroll
        for (int s = 0; s < 2; s++) {
            const int lr = s * 32 + lrow;
            const float rinv = strv[p * 64 + lr];
            const float* qr = stQ + p * 4352 + lr * 68 + lcol8 * 8;
            const float4 qa = *(const float4*)qr;
            const float4 qb = *(const float4*)(qr + 4);
            float v1v[8];
            v1v[0] = elu1(qa.x*rinv); v1v[1] = elu1(qa.y*rinv);
            v1v[2] = elu1(qa.z*rinv); v1v[3] = elu1(qa.w*rinv);
            v1v[4] = elu1(qb.x*rinv); v1v[5] = elu1(qb.y*rinv);
            v1v[6] = elu1(qb.z*rinv); v1v[7] = elu1(qb.w*rinv);

            const int vc = lcol8 * 8;
            float dp = v1v[0]*vs_s[vc+0] + v1v[1]*vs_s[vc+1]
                     + v1v[2]*vs_s[vc+2] + v1v[3]*vs_s[vc+3]
                     + v1v[4]*vs_s[vc+4] + v1v[5]*vs_s[vc+5]
                     + v1v[6]*vs_s[vc+6] + v1v[7]*vs_s[vc+7];
            dp += __shfl_xor_sync(0xffffffffu, dp, 1);
            dp += __shfl_xor_sync(0xffffffffu, dp, 2);
            dp += __shfl_xor_sync(0xffffffffu, dp, 4);

            float* vw = &v1d[V1DUP_ADDR(lr, 2 * vc)];
            *(float4*)(vw)      = make_float4(v1v[0], v1v[0], v1v[1], v1v[1]);
            *(float4*)(vw + 4)  = make_float4(v1v[2], v1v[2], v1v[3], v1v[3]);
            *(float4*)(vw + 8)  = make_float4(v1v[4], v1v[4], v1v[5], v1v[5]);
            *(float4*)(vw + 12) = make_float4(v1v[6], v1v[6], v1v[7], v1v[7]);
            if (lcol8 == 0) dpbuf[lr] = dp;
        }
        __syncthreads();

        // ---- GEMV: warp owns 8 rows (rgrp*2 + rr), thread = 2 rows x 8 e ----
        const int row0 = wid * 8 + rgrp * 2;
        const int a0 = V1DUP_ADDR(row0, 0);
        const int a1 = V1DUP_ADDR(row0 + 1, 0);
        u64t acc[2][4] = {};
        #pragma unroll
        for (int d = 0; d < DH; d += 2) {
            const ulonglong2* bp0 = (const ulonglong2*)&ctx_s[d * 96 + egrp * 12];
            const ulonglong2* bp1 = (const ulonglong2*)&ctx_s[(d + 1) * 96 + egrp * 12];
            const ulonglong2 bA = bp0[0], bB = bp0[1];
            const ulonglong2 cA = bp1[0], cB = bp1[1];
            const ulonglong2 x0 = *(const ulonglong2*)&v1d[a0 + 2 * d];
            const ulonglong2 x1 = *(const ulonglong2*)&v1d[a1 + 2 * d];
            fma2(acc[0][0], x0.x, bA.x); fma2(acc[0][1], x0.x, bA.y);
            fma2(acc[0][2], x0.x, bB.x); fma2(acc[0][3], x0.x, bB.y);
            fma2(acc[0][0], x0.y, cA.x); fma2(acc[0][1], x0.y, cA.y);
            fma2(acc[0][2], x0.y, cB.x); fma2(acc[0][3], x0.y, cB.y);
            fma2(acc[1][0], x1.x, bA.x); fma2(acc[1][1], x1.x, bA.y);
            fma2(acc[1][2], x1.x, bB.x); fma2(acc[1][3], x1.x, bB.y);
            fma2(acc[1][0], x1.y, cA.x); fma2(acc[1][1], x1.y, cA.y);
            fma2(acc[1][2], x1.y, cB.x); fma2(acc[1][3], x1.y, cB.y);
        }

        // ---- tail: Dinv scale, project -> mobius(0.5) -> project, store ----
        #pragma unroll
        for (int rr = 0; rr < 2; rr++) {
            const int lr = row0 + rr;
            const int n  = n0 + it * 64 + lr;
            float x[8];
            upk2(acc[rr][0], x[0], x[1]); upk2(acc[rr][1], x[2], x[3]);
            upk2(acc[rr][2], x[4], x[5]); upk2(acc[rr][3], x[6], x[7]);

            const float dp = dpbuf[lr];
            const float Dinv = 1.f / ((dp == 0.f) ? 1e-5f : dp);
            float n2 = 0.f;
            #pragma unroll
            for (int j = 0; j < 8; j++) { x[j] *= Dinv; n2 += x[j] * x[j]; }
            n2 += __shfl_xor_sync(0xffffffffu, n2, 1);
            n2 += __shfl_xor_sync(0xffffffffu, n2, 2);
            n2 += __shfl_xor_sync(0xffffffffu, n2, 4);

            const float norm = fmaxf(sqrtf(n2), 1e-15f);
            const float scl  = (norm > maxnorm) ? (maxnorm / norm) : 1.f;
            const float xn   = fmaxf(norm * scl, 1e-15f);
            float tk;
            if (hyp) {
                const float u_ = atanhf(fminf(sk * xn, 1.f - 1e-7f));
                tk = tanhf(0.5f * u_) / sk;
            } else {
                const float u_ = atanf(sk * xn);
                tk = tanf(0.5f * u_) / sk;
            }
            const float s2   = tk / xn;
            const float nrm2 = fmaxf(fabsf(tk), 1e-15f);
            const float scl2 = (nrm2 > maxnorm) ? (maxnorm / nrm2) : 1.f;
            const float st   = scl * s2 * scl2;

            float* o = Op + (size_t)n * DH + e0;
            *(float4*)(o)     = make_float4(x[0]*st, x[1]*st, x[2]*st, x[3]*st);
            *(float4*)(o + 4) = make_float4(x[4]*st, x[5]*st, x[6]*st, x[7]*st);
        }
    }
}

extern "C" void kernel_launch(void* const* d_in, const int* in_sizes, int n_in,
                              void* d_out, int out_size)
{
    const float* Q    = (const float*)d_in[0];
    const float* K    = (const float*)d_in[1];
    const float* V    = (const float*)d_in[2];
    const float* mask = (const float*)d_in[3];
    const float* c    = (const float*)d_in[4];
    const int csize = in_sizes[4];
    const int N     = in_sizes[3];
    const int BH    = in_sizes[0] / (N * DH);

    int splits = NSPLIT;
    while (splits > 1 && (N % (splits * 32) != 0)) splits >>= 1;
    int chunks = NSPLIT;
    while (chunks > 1 && (N % (chunks * 64) != 0)) chunks >>= 1;

    cudaFuncSetAttribute(ctx_kernel, cudaFuncAttributeMaxDynamicSharedMemorySize,
                         K1_FLOATS * sizeof(float));
    cudaFuncSetAttribute(out_kernel, cudaFuncAttributeMaxDynamicSharedMemorySize,
                         K2_FLOATS * sizeof(float));

    dim3 g1(splits, BH);
    ctx_kernel<<<g1, 256, K1_FLOATS * sizeof(float)>>>(K, V, mask, c, csize, N);
    dim3 g2(chunks, BH);
    out_kernel<<<g2, 256, K2_FLOATS * sizeof(float)>>>(Q, c, csize, N, splits, (float*)d_out);
}

// round 5
// speedup vs baseline: 1.9695x; 1.1578x over previous
#include <cuda_runtime.h>

#define DH 64
#define MAX_BH 128
#define MAX_N 8192
#define NSPLIT 8

// ---- scratch (static __device__: no allocation) ----
__device__ float g_ctxp[NSPLIT * MAX_BH * DH * DH];  // per-split ctx partials
__device__ float g_vsump[NSPLIT * MAX_BH * DH];      // per-split vsum partials
__device__ float g_rinv[MAX_BH * MAX_N];             // per-row 1/denom (from V)

typedef unsigned long long u64t;

__device__ __forceinline__ u64t pk2(float lo, float hi) {
    u64t r; asm("mov.b64 %0, {%1, %2};" : "=l"(r) : "f"(lo), "f"(hi)); return r;
}
__device__ __forceinline__ void upk2(u64t v, float& lo, float& hi) {
    asm("mov.b64 {%0, %1}, %2;" : "=f"(lo), "=f"(hi) : "l"(v));
}
__device__ __forceinline__ void fma2(u64t& acc, u64t a, u64t b) {
    asm("fma.rn.f32x2 %0, %1, %2, %0;" : "+l"(acc) : "l"(a), "l"(b));
}
__device__ __forceinline__ float elu1(float v) { return v > 0.f ? v + 1.f : __expf(v); }

__device__ __forceinline__ unsigned smem_u32(const void* p) {
    return (unsigned)__cvta_generic_to_shared(p);
}
__device__ __forceinline__ void cp16(unsigned s, const float* g) {
    asm volatile("cp.async.cg.shared.global [%0], [%1], 16;" :: "r"(s), "l"(g));
}
#define CP_COMMIT() asm volatile("cp.async.commit_group;" ::: "memory")
#define CP_WAIT(n)  asm volatile("cp.async.wait_group %0;" :: "n"(n) : "memory")

// ===========================================================================
// K1: ctx[d][e] = sum_n v2[n,d]*x[n,e], vsum[d] = sum_n v2[n,d]; stash rinv.
// Software-pipelined: one __syncthreads per tile; GEMM(t-1) and EW(t) run in
// the same issue window on double-buffered v2d/x_s, hiding EW latency chains
// under FFMA2 issue. cp.async stages hide global latency.
// ===========================================================================
#define K1_STV   0            // 2*32*68 = 4352
#define K1_STK   4352         // 4352
#define K1_STM   8704         // 64
#define K1_V2D   8768         // 2*5120 = 10240 (dup v2, double-buffered)
#define K1_XS    19008        // 2*3072 = 6144 (raw x, double-buffered)
#define K1_FLOATS 25152       // 100608 bytes

__global__ void __launch_bounds__(256, 2)
ctx_kernel(const float* __restrict__ Kg, const float* __restrict__ Vg,
           const float* __restrict__ mask, const float* __restrict__ c,
           int csize, int N)
{
    extern __shared__ float sm[];
    float* stV = sm + K1_STV;
    float* stK = sm + K1_STK;
    float* stM = sm + K1_STM;
    float* v2d = sm + K1_V2D;
    float* x_s = sm + K1_XS;

    const int split = blockIdx.x, bh = blockIdx.y;
    const int rows  = N / gridDim.x;
    const int n0    = split * rows;
    const float k   = (csize > 1) ? c[bh % csize] : c[0];

    const int tid   = threadIdx.x;
    const int lrow  = tid >> 3;
    const int lcol8 = tid & 7;
    const int wid   = tid >> 5, lane = tid & 31;
    const int pairid = wid >> 1, dhalf = wid & 1;
    const int dgrp = lane >> 3, egrp = lane & 7;
    const int gd   = dhalf * 4 + dgrp;

    const float* Kp = Kg + (size_t)bh * N * DH;
    const float* Vp = Vg + (size_t)bh * N * DH;

    const int pr_r0  = tid >> 4;
    const int pr_off = (tid & 15) * 4;

    auto prefetch = [&](int t0, int p) {
        const float* gv = Vp + (size_t)(n0 + t0) * DH;
        const float* gk = Kp + (size_t)(n0 + t0) * DH;
        const unsigned sv = smem_u32(stV + p * 2176);
        const unsigned sk = smem_u32(stK + p * 2176);
        cp16(sv + (pr_r0 * 68 + pr_off) * 4,        gv + pr_r0 * DH + pr_off);
        cp16(sv + ((pr_r0 + 16) * 68 + pr_off) * 4, gv + (pr_r0 + 16) * DH + pr_off);
        cp16(sk + (pr_r0 * 68 + pr_off) * 4,        gk + pr_r0 * DH + pr_off);
        cp16(sk + ((pr_r0 + 16) * 68 + pr_off) * 4, gk + (pr_r0 + 16) * DH + pr_off);
        if (tid < 8) cp16(smem_u32(stM + p * 32) + tid * 16, mask + n0 + t0 + tid * 4);
    };

    u64t acc[8][4] = {};
    float vsum[8] = {0.f,0.f,0.f,0.f,0.f,0.f,0.f,0.f};

    auto gemm_step = [&](int buf) {
        const float* v2b = v2d + buf * 5120;
        const float* xb  = x_s + buf * 3072;
        #pragma unroll
        for (int tt8 = 0; tt8 < 8; tt8++) {
            const int tt = pairid * 8 + tt8;
            const ulonglong2* ap = (const ulonglong2*)&v2b[tt * 160 + gd * 20];
            const ulonglong2 a01 = ap[0], a23 = ap[1], a45 = ap[2], a67 = ap[3];
            const ulonglong2* bp = (const ulonglong2*)&xb[tt * 96 + egrp * 12];
            const ulonglong2 b03 = bp[0], b47 = bp[1];
            const u64t A[8] = {a01.x, a01.y, a23.x, a23.y, a45.x, a45.y, a67.x, a67.y};
            const u64t B[4] = {b03.x, b03.y, b47.x, b47.y};
            #pragma unroll
            for (int dd = 0; dd < 8; dd++) {
                fma2(acc[dd][0], A[dd], B[0]);
                fma2(acc[dd][1], A[dd], B[1]);
                fma2(acc[dd][2], A[dd], B[2]);
                fma2(acc[dd][3], A[dd], B[3]);
            }
        }
    };

    const int T = rows / 32;
    prefetch(0, 0);
    CP_COMMIT();

    for (int t = 0; t < T; t++) {
        CP_WAIT(0);
        __syncthreads();   // stage t visible; prev GEMM+EW of all warps done
        if (t + 1 < T) { prefetch((t + 1) * 32, (t + 1) & 1); CP_COMMIT(); }

        const int pb = t & 1;
        // EW input loads first (from completed stage) so they overlap GEMM
        const float* vr = stV + pb * 2176 + lrow * 68 + lcol8 * 8;
        const float4 va = *(const float4*)vr;
        const float4 vb = *(const float4*)(vr + 4);
        const float* kr = stK + pb * 2176 + lrow * 68 + lcol8 * 8;
        const float4 ka = *(const float4*)kr;
        const float4 kb = *(const float4*)(kr + 4);
        const float m   = stM[pb * 32 + lrow];

        // GEMM on previous tile's buffers (independent of EW above)
        if (t > 0) gemm_step(pb ^ 1);

        // ---- EW compute + stores into buffers pb ----
        const int n = n0 + t * 32 + lrow;
        float ss = va.x*va.x + va.y*va.y + va.z*va.z + va.w*va.w
                 + vb.x*vb.x + vb.y*vb.y + vb.z*vb.z + vb.w*vb.w;
        ss += __shfl_xor_sync(0xffffffffu, ss, 1);
        ss += __shfl_xor_sync(0xffffffffu, ss, 2);
        ss += __shfl_xor_sync(0xffffffffu, ss, 4);
        const float denom = fmaxf(fmaf(k, ss, 1.f), 1e-15f);
        const float rinv  = 1.f / denom;
        const float g     = 2.f * rinv;
        const float gm1   = g - 1.f;
        const float sgn   = (gm1 >= 0.f) ? 1.f : -1.f;
        const float d2    = sgn * fmaxf(fabsf(gm1), 1e-10f);
        const float xs    = g / d2 * m;
        const float d2m   = d2 * m;

        float* xw = &x_s[pb * 3072 + lrow * 96 + lcol8 * 12];
        *(float4*)(xw)     = make_float4(va.x*xs, va.y*xs, va.z*xs, va.w*xs);
        *(float4*)(xw + 4) = make_float4(vb.x*xs, vb.y*xs, vb.z*xs, vb.w*xs);

        float w[8];
        w[0] = d2m*elu1(ka.x*rinv); w[1] = d2m*elu1(ka.y*rinv);
        w[2] = d2m*elu1(ka.z*rinv); w[3] = d2m*elu1(ka.w*rinv);
        w[4] = d2m*elu1(kb.x*rinv); w[5] = d2m*elu1(kb.y*rinv);
        w[6] = d2m*elu1(kb.z*rinv); w[7] = d2m*elu1(kb.w*rinv);
        float* vw = &v2d[pb * 5120 + lrow * 160 + lcol8 * 20];
        *(float4*)(vw)      = make_float4(w[0], w[0], w[1], w[1]);
        *(float4*)(vw + 4)  = make_float4(w[2], w[2], w[3], w[3]);
        *(float4*)(vw + 8)  = make_float4(w[4], w[4], w[5], w[5]);
        *(float4*)(vw + 12) = make_float4(w[6], w[6], w[7], w[7]);
        #pragma unroll
        for (int j = 0; j < 8; j++) vsum[j] += w[j];

        if (lcol8 == 0) g_rinv[(size_t)bh * N + n] = rinv;
    }
    __syncthreads();           // EW(T-1) writes visible
    gemm_step((T - 1) & 1);    // drain
    __syncthreads();           // all GEMM reads done before buffer reuse

    // ---- reduce the 4 warp-pair copies via smem, write split partial ----
    float* red = v2d;
    #pragma unroll
    for (int p = 0; p < 4; p++) {
        if (pairid == p) {
            #pragma unroll
            for (int dd = 0; dd < 8; dd++) {
                #pragma unroll
                for (int ee = 0; ee < 4; ee++) {
                    float f0, f1; upk2(acc[dd][ee], f0, f1);
                    const int idx = (gd * 8 + dd) * 64 + egrp * 8 + ee * 2;
                    if (p == 0) { red[idx] = f0; red[idx + 1] = f1; }
                    else        { red[idx] += f0; red[idx + 1] += f1; }
                }
            }
        }
        __syncthreads();
    }
    float* dst = g_ctxp + ((size_t)bh * NSPLIT + split) * (DH * DH);
    for (int i = tid; i < DH * DH; i += 256) dst[i] = red[i];

    // ---- vsum partial ----
    float* vb2 = x_s;
    #pragma unroll
    for (int j = 0; j < 8; j++) vb2[lrow * 64 + lcol8 * 8 + j] = vsum[j];
    __syncthreads();
    if (tid < DH) {
        float s = 0.f;
        #pragma unroll
        for (int r = 0; r < 32; r++) s += vb2[r * 64 + tid];
        g_vsump[((size_t)bh * NSPLIT + split) * DH + tid] = s;
    }
}

// ===========================================================================
// K2: fused split-reduce prologue + per-row X = (v1@ctx)/(v1.vsum) + geometry.
// 128-row tiles, 4n x 8e thread tiles (LDS ratio 0.25). v1 stored RAW with
// row stride 70 (4-apart rows hit banks {0,24,16,8}: conflict-free) -> smem
// 61KB -> 3 CTAs/SM for latency hiding.
// ===========================================================================
#define V1S 70
#define K2_CTX  0                 // 64*96 = 6144
#define K2_V1   6144              // 128*70 = 8960
#define K2_DP   15104             // 128
#define K2_VS   15232             // 64
#define K2_FLOATS 15296           // 61184 bytes

__global__ void __launch_bounds__(256, 3)
out_kernel(const float* __restrict__ Qg, const float* __restrict__ c,
           int csize, int N, int splits, float* __restrict__ out)
{
    extern __shared__ float sm[];
    float* ctx_s = sm + K2_CTX;
    float* v1s   = sm + K2_V1;
    float* dpbuf = sm + K2_DP;
    float* vs_s  = sm + K2_VS;

    const int chunk = blockIdx.x, bh = blockIdx.y;
    const int rows  = N / gridDim.x;
    const int n0    = chunk * rows;
    const float k   = (csize > 1) ? c[bh % csize] : c[0];
    const float sk  = sqrtf(fabsf(k) + 1e-15f);
    const float maxnorm = (k < 0.f) ? (1.f - 0.004f) / sk : 1e15f;
    const bool  hyp = (k < 0.f);

    const int tid   = threadIdx.x;
    const int lrow  = tid >> 3, lcol8 = tid & 7;
    const int wid   = tid >> 5, lane = tid & 31;
    const int rgrp  = lane >> 3, egrp = lane & 7;
    const int e0    = egrp * 8;

    const float* Qp = Qg + (size_t)bh * N * DH;
    const float* rv = g_rinv + (size_t)bh * N;
    float*       Op = out + (size_t)bh * N * DH;

    // ---- fused reduce of K1 split partials (L2-hot) ----
    const float* bctx = g_ctxp + (size_t)bh * NSPLIT * DH * DH;
    for (int i = tid; i < DH * DH; i += 256) {
        float s = 0.f;
        for (int p = 0; p < splits; p++) s += bctx[p * DH * DH + i];
        const int d = i >> 6, e = i & 63;
        ctx_s[d * 96 + (e >> 3) * 12 + (e & 7)] = s;
    }
    if (tid < DH) {
        float s = 0.f;
        for (int p = 0; p < splits; p++) s += g_vsump[((size_t)bh * NSPLIT + p) * DH + tid];
        vs_s[tid] = s;
    }
    __syncthreads();

    const int nIter = rows / 128;
    for (int it = 0; it < nIter; it++) {
        const int base = n0 + it * 128;

        // ---- elementwise: v1 = elu(Q*rinv)+1 (raw store), dp = v1.vsum ----
        #pragma unroll
        for (int s = 0; s < 4; s++) {
            const int lr = s * 32 + lrow;
            const int n  = base + lr;
            const float rinv = rv[n];
            const size_t nb = (size_t)n * DH + lcol8 * 8;
            const float4 qa = *(const float4*)(Qp + nb);
            const float4 qb = *(const float4*)(Qp + nb + 4);
            float v1v[8];
            v1v[0] = elu1(qa.x*rinv); v1v[1] = elu1(qa.y*rinv);
            v1v[2] = elu1(qa.z*rinv); v1v[3] = elu1(qa.w*rinv);
            v1v[4] = elu1(qb.x*rinv); v1v[5] = elu1(qb.y*rinv);
            v1v[6] = elu1(qb.z*rinv); v1v[7] = elu1(qb.w*rinv);

            const int vc = lcol8 * 8;
            float dp = v1v[0]*vs_s[vc+0] + v1v[1]*vs_s[vc+1]
                     + v1v[2]*vs_s[vc+2] + v1v[3]*vs_s[vc+3]
                     + v1v[4]*vs_s[vc+4] + v1v[5]*vs_s[vc+5]
                     + v1v[6]*vs_s[vc+6] + v1v[7]*vs_s[vc+7];
            dp += __shfl_xor_sync(0xffffffffu, dp, 1);
            dp += __shfl_xor_sync(0xffffffffu, dp, 2);
            dp += __shfl_xor_sync(0xffffffffu, dp, 4);

            float* vw = &v1s[lr * V1S + vc];
            *(float2*)(vw)     = make_float2(v1v[0], v1v[1]);
            *(float2*)(vw + 2) = make_float2(v1v[2], v1v[3]);
            *(float2*)(vw + 4) = make_float2(v1v[4], v1v[5]);
            *(float2*)(vw + 6) = make_float2(v1v[6], v1v[7]);
            if (lcol8 == 0) dpbuf[lr] = dp;
        }
        __syncthreads();

        // ---- GEMV: thread = 4 rows x 8 e ----
        const int row0 = wid * 16 + rgrp * 4;
        u64t acc[4][4] = {};
        #pragma unroll
        for (int d = 0; d < DH; d += 2) {
            const ulonglong2* bp0 = (const ulonglong2*)&ctx_s[d * 96 + egrp * 12];
            const ulonglong2* bp1 = (const ulonglong2*)&ctx_s[(d + 1) * 96 + egrp * 12];
            const ulonglong2 bA = bp0[0], bB = bp0[1];
            const ulonglong2 cA = bp1[0], cB = bp1[1];
            #pragma unroll
            for (int rr = 0; rr < 4; rr++) {
                const u64t ar = *(const u64t*)&v1s[(row0 + rr) * V1S + d];
                float a0, a1; upk2(ar, a0, a1);
                const u64t aa0 = pk2(a0, a0), aa1 = pk2(a1, a1);
                fma2(acc[rr][0], aa0, bA.x); fma2(acc[rr][1], aa0, bA.y);
                fma2(acc[rr][2], aa0, bB.x); fma2(acc[rr][3], aa0, bB.y);
                fma2(acc[rr][0], aa1, cA.x); fma2(acc[rr][1], aa1, cA.y);
                fma2(acc[rr][2], aa1, cB.x); fma2(acc[rr][3], aa1, cB.y);
            }
        }

        // ---- tail: Dinv scale, project -> mobius(0.5) -> project, store ----
        #pragma unroll
        for (int rr = 0; rr < 4; rr++) {
            const int lr = row0 + rr;
            const int n  = base + lr;
            float x[8];
            upk2(acc[rr][0], x[0], x[1]); upk2(acc[rr][1], x[2], x[3]);
            upk2(acc[rr][2], x[4], x[5]); upk2(acc[rr][3], x[6], x[7]);

            const float dp = dpbuf[lr];
            const float Dinv = 1.f / ((dp == 0.f) ? 1e-5f : dp);
            float n2 = 0.f;
            #pragma unroll
            for (int j = 0; j < 8; j++) { x[j] *= Dinv; n2 += x[j] * x[j]; }
            n2 += __shfl_xor_sync(0xffffffffu, n2, 1);
            n2 += __shfl_xor_sync(0xffffffffu, n2, 2);
            n2 += __shfl_xor_sync(0xffffffffu, n2, 4);

            const float norm = fmaxf(sqrtf(n2), 1e-15f);
            const float scl  = (norm > maxnorm) ? (maxnorm / norm) : 1.f;
            const float xn   = fmaxf(norm * scl, 1e-15f);
            float tk;
            if (hyp) {
                const float u_ = atanhf(fminf(sk * xn, 1.f - 1e-7f));
                tk = tanhf(0.5f * u_) / sk;
            } else {
                const float u_ = atanf(sk * xn);
                tk = tanf(0.5f * u_) / sk;
            }
            const float s2   = tk / xn;
            const float nrm2 = fmaxf(fabsf(tk), 1e-15f);
            const float scl2 = (nrm2 > maxnorm) ? (maxnorm / nrm2) : 1.f;
            const float st   = scl * s2 * scl2;

            float* o = Op + (size_t)n * DH + e0;
            *(float4*)(o)     = make_float4(x[0]*st, x[1]*st, x[2]*st, x[3]*st);
            *(float4*)(o + 4) = make_float4(x[4]*st, x[5]*st, x[6]*st, x[7]*st);
        }
        __syncthreads();
    }
}

extern "C" void kernel_launch(void* const* d_in, const int* in_sizes, int n_in,
                              void* d_out, int out_size)
{
    const float* Q    = (const float*)d_in[0];
    const float* K    = (const float*)d_in[1];
    const float* V    = (const float*)d_in[2];
    const float* mask = (const float*)d_in[3];
    const float* c    = (const float*)d_in[4];
    const int csize = in_sizes[4];
    const int N     = in_sizes[3];
    const int BH    = in_sizes[0] / (N * DH);

    int splits = NSPLIT;
    while (splits > 1 && (N % (splits * 32) != 0)) splits >>= 1;
    int chunks = NSPLIT;
    while (chunks > 1 && (N % (chunks * 128) != 0)) chunks >>= 1;

    cudaFuncSetAttribute(ctx_kernel, cudaFuncAttributeMaxDynamicSharedMemorySize,
                         K1_FLOATS * sizeof(float));
    cudaFuncSetAttribute(out_kernel, cudaFuncAttributeMaxDynamicSharedMemorySize,
                         K2_FLOATS * sizeof(float));

    dim3 g1(splits, BH);
    ctx_kernel<<<g1, 256, K1_FLOATS * sizeof(float)>>>(K, V, mask, c, csize, N);
    dim3 g2(chunks, BH);
    out_kernel<<<g2, 256, K2_FLOATS * sizeof(float)>>>(Q, c, csize, N, splits, (float*)d_out);
}